// round 14
// baseline (speedup 1.0000x reference)
#include <cuda_runtime.h>
#include <cstddef>

// Fixed shapes
constexpr int B = 32;
constexpr int C = 256;
constexpr int H = 64;
constexpr int HW = H * H;           // 4096 pixels
constexpr int N = 2048;             // anchors per batch
constexpr int CHUNK = 4;            // channels per tile
constexpr int NCHUNKS = C / CHUNK;  // 64
constexpr int TILES = B * NCHUNKS;  // 2048 tiles
constexpr int THREADS = 1024;       // 32 warps: 24 consumer + 8 producer
constexpr int PROD_T0 = 768;        // first producer thread
constexpr int NPROD   = THREADS - PROD_T0;   // 256 producer threads
constexpr int NCONS   = PROD_T0;             // 768 consumer threads
constexpr size_t SMEM_BYTES = 2ull * HW * sizeof(float4);  // 128 KB ping-pong

__device__ __forceinline__ float4 lerp4(float4 a, float4 b, float t) {
    return make_float4(fmaf(b.x - a.x, t, a.x),
                       fmaf(b.y - a.y, t, a.y),
                       fmaf(b.z - a.z, t, a.z),
                       fmaf(b.w - a.w, t, a.w));
}

__global__ __launch_bounds__(THREADS, 1)
void bilinear_gather_kernel(const float* __restrict__ fm,
                            const float* __restrict__ anchors,
                            float* __restrict__ out)
{
    extern __shared__ float4 sbuf[];   // [2][4096], pixel-major {c0..c3}

    const int tid = threadIdx.x;
    const int nb  = gridDim.x;

    // Balanced static partition of tiles over persistent CTAs.
    const int lo = (int)(((long long)blockIdx.x       * TILES) / nb);
    const int hi = (int)(((long long)(blockIdx.x + 1) * TILES) / nb);

    const bool producer = (tid >= PROD_T0);

    // ---- Prologue: producers stage the first tile.
    if (producer && lo < hi) {
        const int t = lo;
        float4* __restrict__ buf = sbuf + (t & 1) * HW;
        const float* __restrict__ src =
            fm + ((size_t)(t >> 6) * C + (size_t)(t & 63) * CHUNK) * HW;
        const int pt = tid - PROD_T0;
        #pragma unroll 4
        for (int i = 0; i < HW / NPROD; ++i) {
            const int p = pt + i * NPROD;   // consecutive lanes -> consecutive p
            float4 v;
            v.x = src[0 * HW + p];
            v.y = src[1 * HW + p];
            v.z = src[2 * HW + p];
            v.w = src[3 * HW + p];
            buf[p] = v;                     // STS.128, conflict-free
        }
    }

    for (int t = lo; t < hi; ++t) {
        // Handoff: buf[t&1] is full; buf[(t+1)&1] was drained in iter t-1.
        __syncthreads();

        if (producer) {
            // Stage tile t+1 while consumers gather tile t.
            if (t + 1 < hi) {
                const int tn = t + 1;
                float4* __restrict__ buf = sbuf + (tn & 1) * HW;
                const float* __restrict__ src =
                    fm + ((size_t)(tn >> 6) * C + (size_t)(tn & 63) * CHUNK) * HW;
                const int pt = tid - PROD_T0;
                #pragma unroll 4
                for (int i = 0; i < HW / NPROD; ++i) {
                    const int p = pt + i * NPROD;
                    float4 v;
                    v.x = src[0 * HW + p];
                    v.y = src[1 * HW + p];
                    v.z = src[2 * HW + p];
                    v.w = src[3 * HW + p];
                    buf[p] = v;
                }
            }
        } else {
            // Gather tile t: math once per anchor, 4x LDS.128, STG.128.
            const float4* __restrict__ buf = sbuf + (t & 1) * HW;
            const int b     = t >> 6;
            const int chunk = t & 63;
            const float2* __restrict__ anc2 =
                reinterpret_cast<const float2*>(anchors + (size_t)b * N * 2);
            float* __restrict__ outb =
                out + (size_t)b * N * C + (size_t)chunk * CHUNK;

            for (int n = tid; n < N; n += NCONS) {
                float2 a = anc2[n];
                float px = fminf(fmaxf(a.x * 63.0f, 0.0f), 63.0f);
                float py = fminf(fmaxf(a.y * 63.0f, 0.0f), 63.0f);

                float fx = floorf(px), fy = floorf(py);
                float cx = ceilf(px),  cy = ceilf(py);  // matches reference
                int xl = (int)fx, yl = (int)fy;
                int xr = (int)cx, yr = (int)cy;
                float dx = px - fx;
                float dy = py - fy;

                float4 vlt = buf[yl * H + xl];
                float4 vrt = buf[yl * H + xr];
                float4 vlb = buf[yr * H + xl];
                float4 vrb = buf[yr * H + xr];

                float4 vt = lerp4(vlt, vrt, dx);
                float4 vb = lerp4(vlb, vrb, dx);
                float4 r  = lerp4(vt, vb, dy);

                *reinterpret_cast<float4*>(outb + (size_t)n * C) = r;
            }
        }
    }
}

extern "C" void kernel_launch(void* const* d_in, const int* in_sizes, int n_in,
                              void* d_out, int out_size)
{
    const float* fm      = (const float*)d_in[0];  // (32,256,64,64) fp32
    const float* anchors = (const float*)d_in[1];  // (32,2048,2) fp32
    float* out           = (float*)d_out;          // (32,2048,256) fp32

    cudaFuncSetAttribute(bilinear_gather_kernel,
                         cudaFuncAttributeMaxDynamicSharedMemorySize,
                         (int)SMEM_BYTES);

    int nsm = 148;
    cudaDeviceGetAttribute(&nsm, cudaDevAttrMultiProcessorCount, 0);

    dim3 grid(nsm);           // persistent: one 128KB CTA per SM
    dim3 block(THREADS);
    bilinear_gather_kernel<<<grid, block, SMEM_BYTES>>>(fm, anchors, out);
}

// round 15
// speedup vs baseline: 1.2432x; 1.2432x over previous
#include <cuda_runtime.h>
#include <cstddef>
#include <cstdint>

// Fixed shapes
constexpr int B = 32;
constexpr int C = 256;
constexpr int H = 64;
constexpr int HW = H * H;           // 4096 pixels
constexpr int N = 2048;             // anchors per batch
constexpr int CHUNK = 4;            // channels per tile
constexpr int NCHUNKS = C / CHUNK;  // 64
constexpr int TILES = B * NCHUNKS;  // 2048 tiles
constexpr int THREADS = 1024;       // 32 warps
constexpr int TILE_FLOATS = CHUNK * HW;               // 16384 floats = 64 KB
constexpr size_t SMEM_BYTES = 2ull * TILE_FLOATS * 4; // 128 KB ping-pong

__device__ __forceinline__ void cp_async16(uint32_t smem_dst, const void* gmem_src) {
    asm volatile("cp.async.cg.shared.global [%0], [%1], 16;"
                 :: "r"(smem_dst), "l"(gmem_src) : "memory");
}
__device__ __forceinline__ void cp_async_commit() {
    asm volatile("cp.async.commit_group;" ::: "memory");
}
__device__ __forceinline__ void cp_async_wait0() {
    asm volatile("cp.async.wait_group 0;" ::: "memory");
}

__global__ __launch_bounds__(THREADS, 1)
void bilinear_gather_kernel(const float* __restrict__ fm,
                            const float* __restrict__ anchors,
                            float* __restrict__ out)
{
    extern __shared__ float sbuf[];   // [2][16384] channel-major (= gmem layout)

    const int tid = threadIdx.x;
    const int nb  = gridDim.x;

    // Balanced static partition of tiles over persistent CTAs.
    const int lo = (int)(((long long)blockIdx.x       * TILES) / nb);
    const int hi = (int)(((long long)(blockIdx.x + 1) * TILES) / nb);
    if (lo >= hi) return;

    const uint32_t sbase = (uint32_t)__cvta_generic_to_shared(sbuf);

    // ---- Prologue: async-copy first tile (contiguous 64 KB: channel-major
    // smem layout == gmem layout, no transpose needed).
    {
        const char* src = (const char*)(fm + (size_t)lo * TILE_FLOATS);
        const uint32_t dst = sbase + (uint32_t)((lo & 1) * TILE_FLOATS * 4);
        #pragma unroll
        for (int i = 0; i < TILE_FLOATS / 4 / THREADS; ++i) {   // 4 ops/thread
            const int off = (tid + i * THREADS) * 16;
            cp_async16(dst + off, src + off);
        }
        cp_async_commit();
    }

    for (int t = lo; t < hi; ++t) {
        // Tile t's copies done (this thread) ...
        cp_async_wait0();
        // ... and for all threads; also: everyone finished gathering t-1,
        // so buf[(t+1)&1] is free to overwrite.
        __syncthreads();

        // Prefetch tile t+1; latency hides under the gather below.
        if (t + 1 < hi) {
            const char* src = (const char*)(fm + (size_t)(t + 1) * TILE_FLOATS);
            const uint32_t dst = sbase + (uint32_t)(((t + 1) & 1) * TILE_FLOATS * 4);
            #pragma unroll
            for (int i = 0; i < TILE_FLOATS / 4 / THREADS; ++i) {
                const int off = (tid + i * THREADS) * 16;
                cp_async16(dst + off, src + off);
            }
            cp_async_commit();
        }

        // ---- Gather tile t (channel-major, math once per anchor, 16x LDS.32).
        const float* __restrict__ s = sbuf + (t & 1) * TILE_FLOATS;
        const int b     = t >> 6;      // tile -> (batch, chunk)
        const int chunk = t & 63;
        const float2* __restrict__ anc2 =
            reinterpret_cast<const float2*>(anchors + (size_t)b * N * 2);
        float* __restrict__ outb =
            out + (size_t)b * N * C + (size_t)chunk * CHUNK;

        #pragma unroll
        for (int j = 0; j < N / THREADS; ++j) {
            const int n = tid + j * THREADS;

            float2 a = anc2[n];
            float px = fminf(fmaxf(a.x * 63.0f, 0.0f), 63.0f);
            float py = fminf(fmaxf(a.y * 63.0f, 0.0f), 63.0f);

            float fx = floorf(px), fy = floorf(py);
            float cx = ceilf(px),  cy = ceilf(py);  // matches reference
            int xl = (int)fx, yl = (int)fy;
            int xr = (int)cx, yr = (int)cy;
            float dx = px - fx;
            float dy = py - fy;

            const int i_lt = yl * H + xl;
            const int i_rt = yl * H + xr;
            const int i_lb = yr * H + xl;
            const int i_rb = yr * H + xr;

            float res[CHUNK];
            #pragma unroll
            for (int c = 0; c < CHUNK; ++c) {
                const float* __restrict__ sc = s + c * HW;
                float vlt = sc[i_lt];
                float vrt = sc[i_rt];
                float vlb = sc[i_lb];
                float vrb = sc[i_rb];
                float vt = fmaf(vrt - vlt, dx, vlt);
                float vb = fmaf(vrb - vlb, dx, vlb);
                res[c]   = fmaf(vb - vt, dy, vt);
            }

            *reinterpret_cast<float4*>(outb + (size_t)n * C) =
                make_float4(res[0], res[1], res[2], res[3]);   // STG.128
        }
    }
}

extern "C" void kernel_launch(void* const* d_in, const int* in_sizes, int n_in,
                              void* d_out, int out_size)
{
    const float* fm      = (const float*)d_in[0];  // (32,256,64,64) fp32
    const float* anchors = (const float*)d_in[1];  // (32,2048,2) fp32
    float* out           = (float*)d_out;          // (32,2048,256) fp32

    cudaFuncSetAttribute(bilinear_gather_kernel,
                         cudaFuncAttributeMaxDynamicSharedMemorySize,
                         (int)SMEM_BYTES);

    int nsm = 148;
    cudaDeviceGetAttribute(&nsm, cudaDevAttrMultiProcessorCount, 0);

    dim3 grid(nsm);           // persistent: one 128 KB CTA per SM
    dim3 block(THREADS);
    bilinear_gather_kernel<<<grid, block, SMEM_BYTES>>>(fm, anchors, out);
}

// round 16
// speedup vs baseline: 1.4752x; 1.1867x over previous
#include <cuda_runtime.h>
#include <cstddef>

// Fixed shapes
constexpr int B = 32;
constexpr int C = 256;
constexpr int H = 64;
constexpr int HW = H * H;           // 4096 pixels
constexpr int N = 2048;             // anchors per batch
constexpr int CHUNK = 4;            // channels per CTA
constexpr int NCHUNKS = C / CHUNK;  // 64
constexpr int THREADS = 512;        // 16 warps
constexpr size_t SMEM_BYTES = (size_t)HW * CHUNK * 4;  // 64 KB -> 3 CTAs/SM

__device__ __forceinline__ float4 lerp4(float4 a, float4 b, float t) {
    return make_float4(fmaf(b.x - a.x, t, a.x),
                       fmaf(b.y - a.y, t, a.y),
                       fmaf(b.z - a.z, t, a.z),
                       fmaf(b.w - a.w, t, a.w));
}

__global__ __launch_bounds__(THREADS, 3)
void bilinear_gather_kernel(const float* __restrict__ fm,
                            const float* __restrict__ anchors,
                            float* __restrict__ out)
{
    extern __shared__ float4 s4[];   // pixel-major: s4[p] = {c0,c1,c2,c3}

    const int tid   = threadIdx.x;
    const int blk   = blockIdx.x;
    const int b     = blk >> 6;      // / NCHUNKS
    const int chunk = blk & 63;      // % NCHUNKS

    // ---- Stage with register-shuffle transpose (vectorized both ends).
    // 4x4 unit: quad lane qi loads LDG.128 of channel qi, pixels pbase..pbase+3
    // (per warp-instr: 4 channels x 128B contiguous runs -> fully coalesced),
    // transposes in-quad with 4 shfl, stores STS.128 at pixel pbase+qi
    // (consecutive lanes across the warp -> conflict-free).
    {
        const float* __restrict__ src =
            fm + ((size_t)b * C + (size_t)chunk * CHUNK) * HW;
        const int lane = tid & 31;
        const int warp = tid >> 5;       // 0..15
        const int quad = lane >> 2;      // 0..7
        const int qi   = lane & 3;       // channel index for the load

        #pragma unroll
        for (int j = 0; j < 8; ++j) {
            const int pbase = 512 * j + 32 * warp + 4 * quad;
            float4 v = *reinterpret_cast<const float4*>(src + qi * HW + pbase);

            // In-quad 4x4 transpose: after this, lane qi holds
            // {c0,c1,c2,c3} of pixel pbase+qi.
            float s1 = (qi & 1) ? v.x : v.y;
            float r1 = __shfl_xor_sync(0xffffffffu, s1, 1);
            if (qi & 1) v.x = r1; else v.y = r1;
            float s2 = (qi & 1) ? v.z : v.w;
            float r2 = __shfl_xor_sync(0xffffffffu, s2, 1);
            if (qi & 1) v.z = r2; else v.w = r2;

            float s3 = (qi & 2) ? v.x : v.z;
            float r3 = __shfl_xor_sync(0xffffffffu, s3, 2);
            if (qi & 2) v.x = r3; else v.z = r3;
            float s4v = (qi & 2) ? v.y : v.w;
            float r4 = __shfl_xor_sync(0xffffffffu, s4v, 2);
            if (qi & 2) v.y = r4; else v.w = r4;

            s4[pbase + qi] = v;          // warp writes pixels 512j+32w+lane
        }
    }
    __syncthreads();

    const float2* __restrict__ anc2 =
        reinterpret_cast<const float2*>(anchors + (size_t)b * N * 2);
    float* __restrict__ outb = out + (size_t)b * N * C + (size_t)chunk * CHUNK;

    // ---- Gather: one thread per anchor (math once per anchor),
    // 4x LDS.128 per anchor, STG.128 output. 4 unrolled independent iters.
    #pragma unroll
    for (int j = 0; j < N / THREADS; ++j) {
        const int n = tid + j * THREADS;

        float2 a = anc2[n];
        float px = fminf(fmaxf(a.x * 63.0f, 0.0f), 63.0f);
        float py = fminf(fmaxf(a.y * 63.0f, 0.0f), 63.0f);

        float fx = floorf(px), fy = floorf(py);
        float cx = ceilf(px),  cy = ceilf(py);   // matches reference (rb==lt when integral)
        int xl = (int)fx, yl = (int)fy;
        int xr = (int)cx, yr = (int)cy;
        float dx = px - fx;
        float dy = py - fy;

        float4 vlt = s4[yl * H + xl];
        float4 vrt = s4[yl * H + xr];
        float4 vlb = s4[yr * H + xl];
        float4 vrb = s4[yr * H + xr];

        float4 vt = lerp4(vlt, vrt, dx);
        float4 vb = lerp4(vlb, vrb, dx);
        float4 r  = lerp4(vt, vb, dy);

        *reinterpret_cast<float4*>(outb + (size_t)n * C) = r;   // STG.128
    }
}

extern "C" void kernel_launch(void* const* d_in, const int* in_sizes, int n_in,
                              void* d_out, int out_size)
{
    const float* fm      = (const float*)d_in[0];  // (32,256,64,64) fp32
    const float* anchors = (const float*)d_in[1];  // (32,2048,2) fp32
    float* out           = (float*)d_out;          // (32,2048,256) fp32

    cudaFuncSetAttribute(bilinear_gather_kernel,
                         cudaFuncAttributeMaxDynamicSharedMemorySize,
                         (int)SMEM_BYTES);

    dim3 grid(B * NCHUNKS);   // 2048 CTAs
    dim3 block(THREADS);
    bilinear_gather_kernel<<<grid, block, SMEM_BYTES>>>(fm, anchors, out);
}

// round 17
// speedup vs baseline: 1.5821x; 1.0724x over previous
#include <cuda_runtime.h>
#include <cstddef>

// Fixed shapes
constexpr int B = 32;
constexpr int C = 256;
constexpr int H = 64;
constexpr int HW = H * H;           // 4096 pixels
constexpr int N = 2048;             // anchors per batch
constexpr int CHUNK = 4;            // channels per CTA
constexpr int NCHUNKS = C / CHUNK;  // 64
constexpr int THREADS = 512;
constexpr size_t SMEM_BYTES = (size_t)HW * CHUNK * 4;  // 64 KB -> 3 CTAs/SM

// Scratch for sorted anchors (static device arrays: no allocation).
__device__ float2 g_spos[B * N];   // clamped pixel coords, sorted by floor-pixel key
__device__ int    g_sidx[B * N];   // original anchor index

// ---------------------------------------------------------------------------
// Kernel 1: per-batch counting sort of anchors by key = yl*64 + xl.
// grid = 32 (one CTA per batch), 512 threads, 4 anchors/thread.
// ---------------------------------------------------------------------------
__global__ __launch_bounds__(THREADS)
void sort_anchors_kernel(const float* __restrict__ anchors)
{
    __shared__ unsigned int hist[HW];     // 4096 bins (16 KB)
    __shared__ unsigned int part[THREADS];

    const int b   = blockIdx.x;
    const int tid = threadIdx.x;
    const float2* __restrict__ anc2 =
        reinterpret_cast<const float2*>(anchors + (size_t)b * N * 2);

    #pragma unroll
    for (int i = tid; i < HW; i += THREADS) hist[i] = 0u;
    __syncthreads();

    // Load + key + histogram (4 anchors per thread, kept in registers).
    float px[4], py[4];
    int   key[4];
    #pragma unroll
    for (int j = 0; j < 4; ++j) {
        const int n = tid + j * THREADS;
        float2 a = anc2[n];
        px[j] = fminf(fmaxf(a.x * 63.0f, 0.0f), 63.0f);
        py[j] = fminf(fmaxf(a.y * 63.0f, 0.0f), 63.0f);
        key[j] = (int)floorf(py[j]) * H + (int)floorf(px[j]);
        atomicAdd(&hist[key[j]], 1u);
    }
    __syncthreads();

    // Exclusive prefix sum over 4096 bins: thread-local serial (8 bins) +
    // Hillis-Steele inclusive scan over 512 thread totals.
    const int base = tid * 8;
    unsigned int tsum = 0;
    #pragma unroll
    for (int k = 0; k < 8; ++k) {
        unsigned int t = hist[base + k];
        hist[base + k] = tsum;           // local exclusive
        tsum += t;
    }
    part[tid] = tsum;
    __syncthreads();
    for (int off = 1; off < THREADS; off <<= 1) {
        unsigned int v = 0;
        if (tid >= off) v = part[tid - off];
        __syncthreads();
        if (tid >= off) part[tid] += v;
        __syncthreads();
    }
    const unsigned int excl = part[tid] - tsum;   // exclusive across threads
    #pragma unroll
    for (int k = 0; k < 8; ++k) hist[base + k] += excl;
    __syncthreads();

    // Scatter into sorted position (order within a bin is irrelevant:
    // downstream output is keyed by original index).
    #pragma unroll
    for (int j = 0; j < 4; ++j) {
        const int n = tid + j * THREADS;
        const unsigned int pos = atomicAdd(&hist[key[j]], 1u);
        g_spos[b * N + pos] = make_float2(px[j], py[j]);
        g_sidx[b * N + pos] = n;
    }
}

// ---------------------------------------------------------------------------
// Kernel 2: staged bilinear gather, anchors consumed in sorted order.
// ---------------------------------------------------------------------------
__device__ __forceinline__ float4 lerp4(float4 a, float4 b, float t) {
    return make_float4(fmaf(b.x - a.x, t, a.x),
                       fmaf(b.y - a.y, t, a.y),
                       fmaf(b.z - a.z, t, a.z),
                       fmaf(b.w - a.w, t, a.w));
}

__global__ __launch_bounds__(THREADS, 3)
void bilinear_gather_kernel(const float* __restrict__ fm,
                            float* __restrict__ out)
{
    extern __shared__ float4 s4[];   // pixel-major: s4[p] = {c0,c1,c2,c3}

    const int tid   = threadIdx.x;
    const int blk   = blockIdx.x;
    const int b     = blk >> 6;      // / NCHUNKS
    const int chunk = blk & 63;      // % NCHUNKS

    // ---- Stage + transpose to pixel-major (scalar coalesced LDG -> STS.128,
    // consecutive lanes: conflict-free). Proven R10 staging.
    {
        const float* __restrict__ src =
            fm + ((size_t)b * C + (size_t)chunk * CHUNK) * HW;
        #pragma unroll
        for (int p = tid; p < HW; p += THREADS) {
            float4 v;
            v.x = src[0 * HW + p];
            v.y = src[1 * HW + p];
            v.z = src[2 * HW + p];
            v.w = src[3 * HW + p];
            s4[p] = v;
        }
    }
    __syncthreads();

    const float2* __restrict__ spos = g_spos + b * N;
    const int*    __restrict__ sidx = g_sidx + b * N;
    float* __restrict__ outb = out + (size_t)b * N * C + (size_t)chunk * CHUNK;

    // ---- Gather in sorted order: warp's lanes hit near-consecutive pixels
    // -> near-conflict-free LDS.128 (plus broadcasts for shared corners).
    #pragma unroll
    for (int j = 0; j < N / THREADS; ++j) {
        const int n = tid + j * THREADS;

        float2 a  = spos[n];          // already clamped pixel coords
        const int no = sidx[n];

        float fx = floorf(a.x), fy = floorf(a.y);
        float cx = ceilf(a.x),  cy = ceilf(a.y);  // matches reference
        int xl = (int)fx, yl = (int)fy;
        int xr = (int)cx, yr = (int)cy;
        float dx = a.x - fx;
        float dy = a.y - fy;

        float4 vlt = s4[yl * H + xl];
        float4 vrt = s4[yl * H + xr];
        float4 vlb = s4[yr * H + xl];
        float4 vrb = s4[yr * H + xr];

        float4 vt = lerp4(vlt, vrt, dx);
        float4 vb = lerp4(vlb, vrb, dx);
        float4 r  = lerp4(vt, vb, dy);

        // 16B line per anchor; random 'no' vs strided 'n' -- same line count.
        *reinterpret_cast<float4*>(outb + (size_t)no * C) = r;   // STG.128
    }
}

extern "C" void kernel_launch(void* const* d_in, const int* in_sizes, int n_in,
                              void* d_out, int out_size)
{
    const float* fm      = (const float*)d_in[0];  // (32,256,64,64) fp32
    const float* anchors = (const float*)d_in[1];  // (32,2048,2) fp32
    float* out           = (float*)d_out;          // (32,2048,256) fp32

    cudaFuncSetAttribute(bilinear_gather_kernel,
                         cudaFuncAttributeMaxDynamicSharedMemorySize,
                         (int)SMEM_BYTES);

    sort_anchors_kernel<<<B, THREADS>>>(anchors);
    bilinear_gather_kernel<<<B * NCHUNKS, THREADS, SMEM_BYTES>>>(fm, out);
}